// round 13
// baseline (speedup 1.0000x reference)
#include <cuda_runtime.h>
#include <cuda_fp16.h>
#include <cstdint>

// out[e] = sum_d |x[r[e],d] - x[c[e],d]| * w[d] + b[0]
// N_NODES=100000, N_EDGES=600000, D=128 (indices int32: jax x64 disabled)
//
// R12 is at the LTS roofline (391MB @ ~12.5TB/s = 31.2us). v2 locality plan:
//  1) convert: fp32 -> fp16 table (77MB LTS)
//  2) scatter: bucket edges by r>>5 with ONE packed 8B store/edge
//     (fixes R10's 3-store regression); overflow -> exact fp32 inline
//  3) gather: block == bucket, so the bucket's 8KB r-window is L1-resident
//     (r-side L2 traffic 154MB -> ~26MB); c-side uses __ldcs (evict-first)
//     to not pollute L1; warps stride the real count (no padded dead work).
// Per-edge math identical to R9/R12 -> rel_err unchanged (7.6e-4).

#define D_FEAT       128
#define MAX_NODES    100000
#define NB           3125            // buckets of 32 nodes
#define CAP          320             // slots/bucket (mean 192, 9-sigma safe)
#define NSLOTS       (NB * CAP)      // 1,000,000

// fp16 node table: 100000 rows x 128 halves = 16 uint4 per row (256B rows).
__device__ __align__(256) uint4 g_xh[MAX_NODES * (D_FEAT / 8)];
__device__ int g_cnt[NB];
__device__ unsigned long long g_sp[NSLOTS];   // (r&31)<<37 | c<<20 | eid

__global__ __launch_bounds__(256)
void convert_fp16_kernel(const float* __restrict__ x, int n_vec)
{
    const int i = blockIdx.x * blockDim.x + threadIdx.x;
    if (i >= n_vec) return;

    const float4* xf = reinterpret_cast<const float4*>(x);
    const float4 f0 = __ldg(xf + 2 * i);
    const float4 f1 = __ldg(xf + 2 * i + 1);

    const __half2 h0 = __floats2half2_rn(f0.x, f0.y);
    const __half2 h1 = __floats2half2_rn(f0.z, f0.w);
    const __half2 h2 = __floats2half2_rn(f1.x, f1.y);
    const __half2 h3 = __floats2half2_rn(f1.z, f1.w);

    uint4 o;
    o.x = *reinterpret_cast<const unsigned int*>(&h0);
    o.y = *reinterpret_cast<const unsigned int*>(&h1);
    o.z = *reinterpret_cast<const unsigned int*>(&h2);
    o.w = *reinterpret_cast<const unsigned int*>(&h3);
    g_xh[i] = o;
}

__global__ void zero_cnt_kernel()
{
    const int i = blockIdx.x * blockDim.x + threadIdx.x;
    if (i < NB) g_cnt[i] = 0;
}

__global__ __launch_bounds__(256)
void scatter_kernel(const int* __restrict__ r_idx,
                    const int* __restrict__ c_idx,
                    const float* __restrict__ x,
                    const float* __restrict__ w,
                    const float* __restrict__ bia,
                    float* __restrict__ out,
                    int n_edges, int n_nodes)
{
    const int i = blockIdx.x * blockDim.x + threadIdx.x;
    if (i >= n_edges) return;

    int r = __ldg(r_idx + i);
    int c = __ldg(c_idx + i);
    r = min(max(r, 0), n_nodes - 1);
    c = min(max(c, 0), n_nodes - 1);

    const int b = r >> 5;
    const int p = atomicAdd(&g_cnt[b], 1);
    if (p < CAP) {
        const unsigned long long packed =
            ((unsigned long long)(r & 31) << 37) |
            ((unsigned long long)c << 20) |
            (unsigned long long)i;
        g_sp[b * CAP + p] = packed;       // single 8B scattered store
    } else {
        // Exact fp32 fallback (statistically unreachable).
        float s = 0.0f;
        for (int d = 0; d < D_FEAT; ++d)
            s = fmaf(fabsf(__ldg(x + (size_t)r * D_FEAT + d) -
                           __ldg(x + (size_t)c * D_FEAT + d)),
                     __ldg(w + d), s);
        out[i] = s + __ldg(bia);
    }
}

__device__ __forceinline__ __half2 u2h(unsigned int u)
{
    return *reinterpret_cast<const __half2*>(&u);
}

// One block per bucket: the bucket's 32 rows (8KB fp16) become L1-resident.
__global__ __launch_bounds__(256)
void edge_abs_dot_kernel(const float* __restrict__ w,
                         const float* __restrict__ bia,
                         float* __restrict__ out)
{
    const int b    = blockIdx.x;          // bucket id
    const int tid  = threadIdx.x;
    const int wid  = tid >> 5;
    const int lane = tid & 31;
    const int g    = lane >> 4;           // group 0..1
    const int t    = lane & 15;           // position within group

    int cnt = g_cnt[b];
    if (cnt > CAP) cnt = CAP;
    if (cnt == 0) return;

    // Per-lane w slice (dims 8t..8t+7) converted once to half2.
    const float4* w4 = reinterpret_cast<const float4*>(w);
    const float4 wv0 = __ldg(w4 + 2 * t);
    const float4 wv1 = __ldg(w4 + 2 * t + 1);
    const __half2 wh0 = __floats2half2_rn(wv0.x, wv0.y);
    const __half2 wh1 = __floats2half2_rn(wv0.z, wv0.w);
    const __half2 wh2 = __floats2half2_rn(wv1.x, wv1.y);
    const __half2 wh3 = __floats2half2_rn(wv1.z, wv1.w);
    const float   bb  = __ldg(bia);

    const int rbase_off = (b << 5) << 4;  // bucket row base, uint4 units

    // Warps stride over the real count: no padded dead work.
    for (int sbase = wid << 5; sbase < cnt; sbase += 256) {
        const int nvalid = cnt - sbase;                  // >= 1
        const int lslot  = sbase + ((lane < nvalid) ? lane : 0);
        const unsigned long long p = g_sp[b * CAP + lslot];

        const int eid  = (int)(p & 0xFFFFFu);
        const int coff = ((int)(p >> 20) & 0x1FFFF) << 4;
        const int roff = rbase_off + (((int)(p >> 37) & 31) << 4);

        // Depth-2 software pipeline over the 16 j-iterations.
        uint4 a_cur, c_cur, a_nxt, c_nxt;
        {
            const int ro0 = __shfl_sync(0xffffffffu, roff, g);
            const int co0 = __shfl_sync(0xffffffffu, coff, g);
            const int ro1 = __shfl_sync(0xffffffffu, roff, 2 + g);
            const int co1 = __shfl_sync(0xffffffffu, coff, 2 + g);
            a_cur = __ldg(g_xh + ro0 + t);        // r-side: L1-resident
            c_cur = __ldcs(g_xh + co0 + t);       // c-side: evict-first
            a_nxt = __ldg(g_xh + ro1 + t);
            c_nxt = __ldcs(g_xh + co1 + t);
        }

        float res = 0.0f;

        #pragma unroll 4
        for (int j = 0; j < 16; ++j) {
            const uint4 a = a_cur;
            const uint4 c = c_cur;
            a_cur = a_nxt;
            c_cur = c_nxt;
            if (j < 14) {
                const int src = 2 * (j + 2) + g;
                const int ro = __shfl_sync(0xffffffffu, roff, src);
                const int co = __shfl_sync(0xffffffffu, coff, src);
                a_nxt = __ldg(g_xh + ro + t);
                c_nxt = __ldcs(g_xh + co + t);
            }

            const __half2 d0 = __habs2(__hsub2(u2h(a.x), u2h(c.x)));
            const __half2 d1 = __habs2(__hsub2(u2h(a.y), u2h(c.y)));
            const __half2 d2 = __habs2(__hsub2(u2h(a.z), u2h(c.z)));
            const __half2 d3 = __habs2(__hsub2(u2h(a.w), u2h(c.w)));

            __half2 pr = __hmul2(d0, wh0);
            pr = __hfma2(d1, wh1, pr);
            pr = __hfma2(d2, wh2, pr);
            pr = __hfma2(d3, wh3, pr);

            const float2 pf = __half22float2(pr);
            float s = pf.x + pf.y;

            s += __shfl_xor_sync(0xffffffffu, s, 8);
            s += __shfl_xor_sync(0xffffffffu, s, 4);
            s += __shfl_xor_sync(0xffffffffu, s, 2);
            s += __shfl_xor_sync(0xffffffffu, s, 1);

            if (t == j) res = s;      // lane 16g+j holds warp-edge 2j+g
        }

        // Lane (g,t) holds warp-edge m = 2t+g; fetch its eid from lane m.
        const int m    = 2 * t + g;
        const int oeid = __shfl_sync(0xffffffffu, eid, m);
        if (m < nvalid)
            out[oeid] = res + bb;
    }
}

extern "C" void kernel_launch(void* const* d_in, const int* in_sizes, int n_in,
                              void* d_out, int out_size)
{
    const float* x     = (const float*)d_in[0];   // [N_NODES, 128] fp32
    const int*   r_idx = (const int*)d_in[1];     // [E] int32
    const int*   c_idx = (const int*)d_in[2];     // [E] int32
    const float* w     = (const float*)d_in[3];   // [128, 1] fp32
    const float* b     = (const float*)d_in[4];   // [1] fp32
    float*       out   = (float*)d_out;           // [E] fp32

    const int n_edges = in_sizes[1];              // 600000
    int n_nodes = in_sizes[0] / D_FEAT;           // 100000
    if (n_nodes > MAX_NODES) n_nodes = MAX_NODES;

    // 1) fp32 -> fp16 node table
    const int n_vec = n_nodes * (D_FEAT / 8);     // 1.6M uint4
    convert_fp16_kernel<<<(n_vec + 255) / 256, 256>>>(x, n_vec);

    // 2) zero bucket counters
    zero_cnt_kernel<<<(NB + 255) / 256, 256>>>();

    // 3) bucket edges by r>>5 (one packed 8B store per edge)
    scatter_kernel<<<(n_edges + 255) / 256, 256>>>(r_idx, c_idx, x, w, b,
                                                   out, n_edges, n_nodes);

    // 4) gather: one block per bucket
    edge_abs_dot_kernel<<<NB, 256>>>(w, b, out);
}

// round 14
// speedup vs baseline: 1.8052x; 1.8052x over previous
#include <cuda_runtime.h>
#include <cuda_fp16.h>
#include <cstdint>

// out[e] = sum_d |x[r[e],d] - x[c[e],d]| * w[d] + b[0]
// N_NODES=100000, N_EDGES=600000, D=128 (indices int32: jax x64 disabled)
//
// CONVERGED KERNEL (R12 restored; R13 bucket-v2 regressed 1.9x):
//   1) convert: fp32 -> fp16 node table in __device__ scratch
//      (77MB LTS traffic, ~6us, at the measured LTS cap)
//   2) gather: 16 lanes/edge, 4 L1-lines/edge, half2 math, depth-2
//      prefetch (307MB LTS @ 12.1TB/s == HW-measured ~6300B/cyc cap)
// Total 384MB / 12.2TB/s ~= 31.4us floor == measured 31.2us.
// Evaluated and rejected: sub-16-bit storage (error budget), bucket/sort
// locality (2x regression twice: scatter traffic + occupancy collapse),
// scheduling variants (neutral or negative, R4-R11).

#define D_FEAT    128
#define MAX_NODES 100000

// fp16 node table: 100000 rows x 128 halves = 16 uint4 per row (256B rows).
__device__ __align__(256) uint4 g_xh[MAX_NODES * (D_FEAT / 8)];

__global__ __launch_bounds__(256)
void convert_fp16_kernel(const float* __restrict__ x, int n_vec)
{
    const int i = blockIdx.x * blockDim.x + threadIdx.x;
    if (i >= n_vec) return;

    const float4* xf = reinterpret_cast<const float4*>(x);
    const float4 f0 = __ldg(xf + 2 * i);
    const float4 f1 = __ldg(xf + 2 * i + 1);

    const __half2 h0 = __floats2half2_rn(f0.x, f0.y);
    const __half2 h1 = __floats2half2_rn(f0.z, f0.w);
    const __half2 h2 = __floats2half2_rn(f1.x, f1.y);
    const __half2 h3 = __floats2half2_rn(f1.z, f1.w);

    uint4 o;
    o.x = *reinterpret_cast<const unsigned int*>(&h0);
    o.y = *reinterpret_cast<const unsigned int*>(&h1);
    o.z = *reinterpret_cast<const unsigned int*>(&h2);
    o.w = *reinterpret_cast<const unsigned int*>(&h3);
    g_xh[i] = o;
}

__device__ __forceinline__ __half2 u2h(unsigned int u)
{
    return *reinterpret_cast<const __half2*>(&u);
}

__global__ __launch_bounds__(256)
void edge_abs_dot_kernel(const int* __restrict__ r_idx,
                         const int* __restrict__ c_idx,
                         const float* __restrict__ w,
                         const float* __restrict__ b,
                         float* __restrict__ out,
                         int n_edges,
                         int n_nodes)
{
    const int lane  = threadIdx.x & 31;
    const int g     = lane >> 4;        // group 0..1 (one edge each)
    const int t     = lane & 15;        // position within group
    const int gwarp = (blockIdx.x * blockDim.x + threadIdx.x) >> 5;
    const int base  = gwarp << 5;       // 32 edges per warp
    if (base >= n_edges) return;

    // Per-lane w slice (dims 8t..8t+7) converted once to half2.
    const float4* w4 = reinterpret_cast<const float4*>(w);
    const float4 wv0 = __ldg(w4 + 2 * t);
    const float4 wv1 = __ldg(w4 + 2 * t + 1);
    const __half2 wh0 = __floats2half2_rn(wv0.x, wv0.y);
    const __half2 wh1 = __floats2half2_rn(wv0.z, wv0.w);
    const __half2 wh2 = __floats2half2_rn(wv1.x, wv1.y);
    const __half2 wh3 = __floats2half2_rn(wv1.z, wv1.w);
    const float   bb  = __ldg(b);

    // Coalesced index preload; pre-scale to uint4-element offsets so the
    // loop does no multiplies (shfl carries the scaled offset).
    const int eload = min(base + lane, n_edges - 1);
    int ridx = __ldg(r_idx + eload);
    int cidx = __ldg(c_idx + eload);
    ridx = min(max(ridx, 0), n_nodes - 1);
    cidx = min(max(cidx, 0), n_nodes - 1);
    const int roff = ridx << 4;         // row start in uint4 units
    const int coff = cidx << 4;

    // Depth-2 software pipeline: iterations j and j+1 in flight.
    uint4 a_cur, c_cur, a_nxt, c_nxt;
    {
        const int s0 = g;                       // j=0: edge base+g
        const int s1 = 2 + g;                   // j=1: edge base+2+g
        const int ro0 = __shfl_sync(0xffffffffu, roff, s0);
        const int co0 = __shfl_sync(0xffffffffu, coff, s0);
        const int ro1 = __shfl_sync(0xffffffffu, roff, s1);
        const int co1 = __shfl_sync(0xffffffffu, coff, s1);
        a_cur = g_xh[ro0 + t];
        c_cur = g_xh[co0 + t];
        a_nxt = g_xh[ro1 + t];
        c_nxt = g_xh[co1 + t];
    }

    float res = 0.0f;

    #pragma unroll 4
    for (int j = 0; j < 16; ++j) {
        const uint4 a = a_cur;
        const uint4 c = c_cur;
        a_cur = a_nxt;
        c_cur = c_nxt;
        if (j < 14) {
            const int src = 2 * (j + 2) + g;
            const int ro = __shfl_sync(0xffffffffu, roff, src);
            const int co = __shfl_sync(0xffffffffu, coff, src);
            a_nxt = g_xh[ro + t];
            c_nxt = g_xh[co + t];
        }

        // |a - c| in half2 (HABS2 on ALU pipe), 4-term HFMA2 accumulation.
        const __half2 d0 = __habs2(__hsub2(u2h(a.x), u2h(c.x)));
        const __half2 d1 = __habs2(__hsub2(u2h(a.y), u2h(c.y)));
        const __half2 d2 = __habs2(__hsub2(u2h(a.z), u2h(c.z)));
        const __half2 d3 = __habs2(__hsub2(u2h(a.w), u2h(c.w)));

        __half2 p = __hmul2(d0, wh0);
        p = __hfma2(d1, wh1, p);
        p = __hfma2(d2, wh2, p);
        p = __hfma2(d3, wh3, p);

        const float2 pf = __half22float2(p);
        float s = pf.x + pf.y;

        // Reduce within each 16-lane group (2 edges simultaneously), fp32.
        s += __shfl_xor_sync(0xffffffffu, s, 8);
        s += __shfl_xor_sync(0xffffffffu, s, 4);
        s += __shfl_xor_sync(0xffffffffu, s, 2);
        s += __shfl_xor_sync(0xffffffffu, s, 1);

        if (t == j) res = s;    // lane 16g+j holds edge base+2j+g
    }

    // Lane L (g=L>>4, t=L&15) stores edge base + 2t + g.
    // All 32 targets lie in one 128B line -> single store wavefront.
    const int estore = base + 2 * t + g;
    if (estore < n_edges)
        out[estore] = res + bb;
}

extern "C" void kernel_launch(void* const* d_in, const int* in_sizes, int n_in,
                              void* d_out, int out_size)
{
    const float* x     = (const float*)d_in[0];   // [N_NODES, 128] fp32
    const int*   r_idx = (const int*)d_in[1];     // [E] int32
    const int*   c_idx = (const int*)d_in[2];     // [E] int32
    const float* w     = (const float*)d_in[3];   // [128, 1] fp32
    const float* b     = (const float*)d_in[4];   // [1] fp32
    float*       out   = (float*)d_out;           // [E] fp32

    const int n_edges = in_sizes[1];              // 600000
    int n_nodes = in_sizes[0] / D_FEAT;           // 100000
    if (n_nodes > MAX_NODES) n_nodes = MAX_NODES;

    // 1) fp32 -> fp16 node table (each thread emits one uint4 = 8 halves)
    const int n_vec = n_nodes * (D_FEAT / 8);     // 1.6M
    convert_fp16_kernel<<<(n_vec + 255) / 256, 256>>>(x, n_vec);

    // 2) edge gather + abs-diff dot
    const int threads = 256;                      // 8 warps/block
    const int edges_per_block = (threads / 32) * 32;   // 256 edges
    const int blocks = (n_edges + edges_per_block - 1) / edges_per_block;
    edge_abs_dot_kernel<<<blocks, threads>>>(r_idx, c_idx, w, b, out,
                                             n_edges, n_nodes);
}

// round 15
// speedup vs baseline: 1.8327x; 1.0152x over previous
#include <cuda_runtime.h>
#include <cuda_fp16.h>
#include <cstdint>

// out[e] = sum_d |x[r[e],d] - x[c[e],d]| * w[d] + b[0]
// N_NODES=100000, N_EDGES=600000, D=128 (indices int32: jax x64 disabled)
//
// CONVERGED KERNEL (R12 config + cache-policy hints):
//   1) convert: fp32 -> fp16 node table in __device__ scratch.
//      fp32 source read with __ldcs (evict-first: dead after conversion,
//      keeps L2 for the fp16 table). 77MB LTS, ~6us at cap.
//   2) gather: 16 lanes/edge, 4 L1-lines/edge, half2 math, depth-2
//      prefetch; out stored with __stcs (never re-read).
//      307MB LTS @ ~12.1TB/s == HW-measured ~6300B/cyc LTS cap.
// Total 384MB / ~12.2TB/s ~= 31.4us floor == measured 31.2-32.0us.
// Rejected paths: sub-16-bit storage (error budget), bucket/sort locality
// (2x regression twice), scheduling variants (flat within noise).

#define D_FEAT    128
#define MAX_NODES 100000

// fp16 node table: 100000 rows x 128 halves = 16 uint4 per row (256B rows).
__device__ __align__(256) uint4 g_xh[MAX_NODES * (D_FEAT / 8)];

__global__ __launch_bounds__(256)
void convert_fp16_kernel(const float* __restrict__ x, int n_vec)
{
    const int i = blockIdx.x * blockDim.x + threadIdx.x;
    if (i >= n_vec) return;

    const float4* xf = reinterpret_cast<const float4*>(x);
    const float4 f0 = __ldcs(xf + 2 * i);       // evict-first: dead data
    const float4 f1 = __ldcs(xf + 2 * i + 1);

    const __half2 h0 = __floats2half2_rn(f0.x, f0.y);
    const __half2 h1 = __floats2half2_rn(f0.z, f0.w);
    const __half2 h2 = __floats2half2_rn(f1.x, f1.y);
    const __half2 h3 = __floats2half2_rn(f1.z, f1.w);

    uint4 o;
    o.x = *reinterpret_cast<const unsigned int*>(&h0);
    o.y = *reinterpret_cast<const unsigned int*>(&h1);
    o.z = *reinterpret_cast<const unsigned int*>(&h2);
    o.w = *reinterpret_cast<const unsigned int*>(&h3);
    g_xh[i] = o;
}

__device__ __forceinline__ __half2 u2h(unsigned int u)
{
    return *reinterpret_cast<const __half2*>(&u);
}

__global__ __launch_bounds__(256)
void edge_abs_dot_kernel(const int* __restrict__ r_idx,
                         const int* __restrict__ c_idx,
                         const float* __restrict__ w,
                         const float* __restrict__ b,
                         float* __restrict__ out,
                         int n_edges,
                         int n_nodes)
{
    const int lane  = threadIdx.x & 31;
    const int g     = lane >> 4;        // group 0..1 (one edge each)
    const int t     = lane & 15;        // position within group
    const int gwarp = (blockIdx.x * blockDim.x + threadIdx.x) >> 5;
    const int base  = gwarp << 5;       // 32 edges per warp
    if (base >= n_edges) return;

    // Per-lane w slice (dims 8t..8t+7) converted once to half2.
    const float4* w4 = reinterpret_cast<const float4*>(w);
    const float4 wv0 = __ldg(w4 + 2 * t);
    const float4 wv1 = __ldg(w4 + 2 * t + 1);
    const __half2 wh0 = __floats2half2_rn(wv0.x, wv0.y);
    const __half2 wh1 = __floats2half2_rn(wv0.z, wv0.w);
    const __half2 wh2 = __floats2half2_rn(wv1.x, wv1.y);
    const __half2 wh3 = __floats2half2_rn(wv1.z, wv1.w);
    const float   bb  = __ldg(b);

    // Coalesced index preload; pre-scale to uint4-element offsets so the
    // loop does no multiplies (shfl carries the scaled offset).
    const int eload = min(base + lane, n_edges - 1);
    int ridx = __ldg(r_idx + eload);
    int cidx = __ldg(c_idx + eload);
    ridx = min(max(ridx, 0), n_nodes - 1);
    cidx = min(max(cidx, 0), n_nodes - 1);
    const int roff = ridx << 4;         // row start in uint4 units
    const int coff = cidx << 4;

    // Depth-2 software pipeline: iterations j and j+1 in flight.
    uint4 a_cur, c_cur, a_nxt, c_nxt;
    {
        const int s0 = g;                       // j=0: edge base+g
        const int s1 = 2 + g;                   // j=1: edge base+2+g
        const int ro0 = __shfl_sync(0xffffffffu, roff, s0);
        const int co0 = __shfl_sync(0xffffffffu, coff, s0);
        const int ro1 = __shfl_sync(0xffffffffu, roff, s1);
        const int co1 = __shfl_sync(0xffffffffu, coff, s1);
        a_cur = g_xh[ro0 + t];
        c_cur = g_xh[co0 + t];
        a_nxt = g_xh[ro1 + t];
        c_nxt = g_xh[co1 + t];
    }

    float res = 0.0f;

    #pragma unroll 4
    for (int j = 0; j < 16; ++j) {
        const uint4 a = a_cur;
        const uint4 c = c_cur;
        a_cur = a_nxt;
        c_cur = c_nxt;
        if (j < 14) {
            const int src = 2 * (j + 2) + g;
            const int ro = __shfl_sync(0xffffffffu, roff, src);
            const int co = __shfl_sync(0xffffffffu, coff, src);
            a_nxt = g_xh[ro + t];
            c_nxt = g_xh[co + t];
        }

        // |a - c| in half2 (HABS2 on ALU pipe), 4-term HFMA2 accumulation.
        const __half2 d0 = __habs2(__hsub2(u2h(a.x), u2h(c.x)));
        const __half2 d1 = __habs2(__hsub2(u2h(a.y), u2h(c.y)));
        const __half2 d2 = __habs2(__hsub2(u2h(a.z), u2h(c.z)));
        const __half2 d3 = __habs2(__hsub2(u2h(a.w), u2h(c.w)));

        __half2 p = __hmul2(d0, wh0);
        p = __hfma2(d1, wh1, p);
        p = __hfma2(d2, wh2, p);
        p = __hfma2(d3, wh3, p);

        const float2 pf = __half22float2(p);
        float s = pf.x + pf.y;

        // Reduce within each 16-lane group (2 edges simultaneously), fp32.
        s += __shfl_xor_sync(0xffffffffu, s, 8);
        s += __shfl_xor_sync(0xffffffffu, s, 4);
        s += __shfl_xor_sync(0xffffffffu, s, 2);
        s += __shfl_xor_sync(0xffffffffu, s, 1);

        if (t == j) res = s;    // lane 16g+j holds edge base+2j+g
    }

    // Lane L (g=L>>4, t=L&15) stores edge base + 2t + g.
    // All 32 targets lie in one 128B line -> single store wavefront.
    // Evict-first: out is never re-read.
    const int estore = base + 2 * t + g;
    if (estore < n_edges)
        __stcs(out + estore, res + bb);
}

extern "C" void kernel_launch(void* const* d_in, const int* in_sizes, int n_in,
                              void* d_out, int out_size)
{
    const float* x     = (const float*)d_in[0];   // [N_NODES, 128] fp32
    const int*   r_idx = (const int*)d_in[1];     // [E] int32
    const int*   c_idx = (const int*)d_in[2];     // [E] int32
    const float* w     = (const float*)d_in[3];   // [128, 1] fp32
    const float* b     = (const float*)d_in[4];   // [1] fp32
    float*       out   = (float*)d_out;           // [E] fp32

    const int n_edges = in_sizes[1];              // 600000
    int n_nodes = in_sizes[0] / D_FEAT;           // 100000
    if (n_nodes > MAX_NODES) n_nodes = MAX_NODES;

    // 1) fp32 -> fp16 node table (each thread emits one uint4 = 8 halves)
    const int n_vec = n_nodes * (D_FEAT / 8);     // 1.6M
    convert_fp16_kernel<<<(n_vec + 255) / 256, 256>>>(x, n_vec);

    // 2) edge gather + abs-diff dot
    const int threads = 256;                      // 8 warps/block
    const int edges_per_block = (threads / 32) * 32;   // 256 edges
    const int blocks = (n_edges + edges_per_block - 1) / edges_per_block;
    edge_abs_dot_kernel<<<blocks, threads>>>(r_idx, c_idx, w, b, out,
                                             n_edges, n_nodes);
}

// round 16
// speedup vs baseline: 1.8345x; 1.0010x over previous
#include <cuda_runtime.h>
#include <cuda_fp16.h>
#include <cstdint>

// out[e] = sum_d |x[r[e],d] - x[c[e],d]| * w[d] + b[0]
// N_NODES=100000, N_EDGES=600000, D=128 (indices int32: jax x64 disabled)
//
// FINAL CONVERGED KERNEL.
//   1) convert: fp32 -> fp16 node table in __device__ scratch (77MB LTS,
//      ~6us at cap; __ldcs on the dead fp32 source).
//   2) gather: 16 lanes/edge, 4 L1-lines/edge, half2 math, depth-2
//      prefetch; 307MB LTS @ ~12.1TB/s == HW LTS cap (~6300B/cyc).
// Analytic floor 384MB / 12.2TB/s = 31.4us; measured 31.2-32.0us.
// Exhausted: lane geometry, load widths, unroll/occupancy/pipeline-depth,
// bucket locality (2x regression twice), sub-fp16 storage (error budget),
// algebraic factoring / tensor cores (blocked by abs()).

#define D_FEAT    128
#define MAX_NODES 100000

// fp16 node table: 100000 rows x 128 halves = 16 uint4 per row (256B rows).
__device__ __align__(256) uint4 g_xh[MAX_NODES * (D_FEAT / 8)];

__global__ __launch_bounds__(512)
void convert_fp16_kernel(const float* __restrict__ x, int n_vec)
{
    const int i = blockIdx.x * blockDim.x + threadIdx.x;
    if (i >= n_vec) return;

    const float4* xf = reinterpret_cast<const float4*>(x);
    const float4 f0 = __ldcs(xf + 2 * i);       // evict-first: dead data
    const float4 f1 = __ldcs(xf + 2 * i + 1);

    const __half2 h0 = __floats2half2_rn(f0.x, f0.y);
    const __half2 h1 = __floats2half2_rn(f0.z, f0.w);
    const __half2 h2 = __floats2half2_rn(f1.x, f1.y);
    const __half2 h3 = __floats2half2_rn(f1.z, f1.w);

    uint4 o;
    o.x = *reinterpret_cast<const unsigned int*>(&h0);
    o.y = *reinterpret_cast<const unsigned int*>(&h1);
    o.z = *reinterpret_cast<const unsigned int*>(&h2);
    o.w = *reinterpret_cast<const unsigned int*>(&h3);
    g_xh[i] = o;
}

__device__ __forceinline__ __half2 u2h(unsigned int u)
{
    return *reinterpret_cast<const __half2*>(&u);
}

__global__ __launch_bounds__(256)
void edge_abs_dot_kernel(const int* __restrict__ r_idx,
                         const int* __restrict__ c_idx,
                         const float* __restrict__ w,
                         const float* __restrict__ b,
                         float* __restrict__ out,
                         int n_edges,
                         int n_nodes)
{
    const int lane  = threadIdx.x & 31;
    const int g     = lane >> 4;        // group 0..1 (one edge each)
    const int t     = lane & 15;        // position within group
    const int gwarp = (blockIdx.x * blockDim.x + threadIdx.x) >> 5;
    const int base  = gwarp << 5;       // 32 edges per warp
    if (base >= n_edges) return;

    // Per-lane w slice (dims 8t..8t+7) converted once to half2.
    const float4* w4 = reinterpret_cast<const float4*>(w);
    const float4 wv0 = __ldg(w4 + 2 * t);
    const float4 wv1 = __ldg(w4 + 2 * t + 1);
    const __half2 wh0 = __floats2half2_rn(wv0.x, wv0.y);
    const __half2 wh1 = __floats2half2_rn(wv0.z, wv0.w);
    const __half2 wh2 = __floats2half2_rn(wv1.x, wv1.y);
    const __half2 wh3 = __floats2half2_rn(wv1.z, wv1.w);
    const float   bb  = __ldg(b);

    // Coalesced index preload; pre-scale to uint4-element offsets so the
    // loop does no multiplies (shfl carries the scaled offset).
    const int eload = min(base + lane, n_edges - 1);
    int ridx = __ldg(r_idx + eload);
    int cidx = __ldg(c_idx + eload);
    ridx = min(max(ridx, 0), n_nodes - 1);
    cidx = min(max(cidx, 0), n_nodes - 1);
    const int roff = ridx << 4;         // row start in uint4 units
    const int coff = cidx << 4;

    // Depth-2 software pipeline: iterations j and j+1 in flight.
    uint4 a_cur, c_cur, a_nxt, c_nxt;
    {
        const int s0 = g;                       // j=0: edge base+g
        const int s1 = 2 + g;                   // j=1: edge base+2+g
        const int ro0 = __shfl_sync(0xffffffffu, roff, s0);
        const int co0 = __shfl_sync(0xffffffffu, coff, s0);
        const int ro1 = __shfl_sync(0xffffffffu, roff, s1);
        const int co1 = __shfl_sync(0xffffffffu, coff, s1);
        a_cur = g_xh[ro0 + t];
        c_cur = g_xh[co0 + t];
        a_nxt = g_xh[ro1 + t];
        c_nxt = g_xh[co1 + t];
    }

    float res = 0.0f;

    #pragma unroll 4
    for (int j = 0; j < 16; ++j) {
        const uint4 a = a_cur;
        const uint4 c = c_cur;
        a_cur = a_nxt;
        c_cur = c_nxt;
        if (j < 14) {
            const int src = 2 * (j + 2) + g;
            const int ro = __shfl_sync(0xffffffffu, roff, src);
            const int co = __shfl_sync(0xffffffffu, coff, src);
            a_nxt = g_xh[ro + t];
            c_nxt = g_xh[co + t];
        }

        // |a - c| in half2 (HABS2 on ALU pipe), 4-term HFMA2 accumulation.
        const __half2 d0 = __habs2(__hsub2(u2h(a.x), u2h(c.x)));
        const __half2 d1 = __habs2(__hsub2(u2h(a.y), u2h(c.y)));
        const __half2 d2 = __habs2(__hsub2(u2h(a.z), u2h(c.z)));
        const __half2 d3 = __habs2(__hsub2(u2h(a.w), u2h(c.w)));

        __half2 p = __hmul2(d0, wh0);
        p = __hfma2(d1, wh1, p);
        p = __hfma2(d2, wh2, p);
        p = __hfma2(d3, wh3, p);

        const float2 pf = __half22float2(p);
        float s = pf.x + pf.y;

        // Reduce within each 16-lane group (2 edges simultaneously), fp32.
        s += __shfl_xor_sync(0xffffffffu, s, 8);
        s += __shfl_xor_sync(0xffffffffu, s, 4);
        s += __shfl_xor_sync(0xffffffffu, s, 2);
        s += __shfl_xor_sync(0xffffffffu, s, 1);

        if (t == j) res = s;    // lane 16g+j holds edge base+2j+g
    }

    // Lane L (g=L>>4, t=L&15) stores edge base + 2t + g.
    // All 32 targets lie in one 128B line -> single store wavefront.
    // Evict-first: out is never re-read.
    const int estore = base + 2 * t + g;
    if (estore < n_edges)
        __stcs(out + estore, res + bb);
}

extern "C" void kernel_launch(void* const* d_in, const int* in_sizes, int n_in,
                              void* d_out, int out_size)
{
    const float* x     = (const float*)d_in[0];   // [N_NODES, 128] fp32
    const int*   r_idx = (const int*)d_in[1];     // [E] int32
    const int*   c_idx = (const int*)d_in[2];     // [E] int32
    const float* w     = (const float*)d_in[3];   // [128, 1] fp32
    const float* b     = (const float*)d_in[4];   // [1] fp32
    float*       out   = (float*)d_out;           // [E] fp32

    const int n_edges = in_sizes[1];              // 600000
    int n_nodes = in_sizes[0] / D_FEAT;           // 100000
    if (n_nodes > MAX_NODES) n_nodes = MAX_NODES;

    // 1) fp32 -> fp16 node table (each thread emits one uint4 = 8 halves)
    const int n_vec = n_nodes * (D_FEAT / 8);     // 1.6M
    convert_fp16_kernel<<<(n_vec + 511) / 512, 512>>>(x, n_vec);

    // 2) edge gather + abs-diff dot
    const int threads = 256;                      // 8 warps/block
    const int edges_per_block = (threads / 32) * 32;   // 256 edges
    const int blocks = (n_edges + edges_per_block - 1) / edges_per_block;
    edge_abs_dot_kernel<<<blocks, threads>>>(r_idx, c_idx, w, b, out,
                                             n_edges, n_nodes);
}

// round 17
// speedup vs baseline: 1.8533x; 1.0103x over previous
#include <cuda_runtime.h>
#include <cuda_fp16.h>
#include <cstdint>

// out[e] = sum_d |x[r[e],d] - x[c[e],d]| * w[d] + b[0]
// N_NODES=100000, N_EDGES=600000, D=128 (indices int32: jax x64 disabled)
//
// FINAL CONVERGED KERNEL (stable across 4 consecutive runs: 31.2-32.0us
// vs 31.4us analytic LTS floor).
//   1) convert: fp32 -> fp16 node table in __device__ scratch (77MB LTS,
//      ~6us at cap; __ldcs on the dead fp32 source).
//   2) gather: 16 lanes/edge, 4 L1-lines/edge, half2 math, depth-2
//      prefetch; 307MB LTS @ ~12.1TB/s == HW LTS cap (~6300B/cyc).
// Exhausted: lane geometry, load widths, unroll/occupancy/pipeline depth,
// bucket locality (2x regression twice), sub-fp16 storage (error budget),
// stream overlap (true dependency), dedup (0.5% collisions), algebraic
// factoring / tensor cores (blocked by abs()).

#define D_FEAT    128
#define MAX_NODES 100000

// fp16 node table: 100000 rows x 128 halves = 16 uint4 per row (256B rows).
__device__ __align__(256) uint4 g_xh[MAX_NODES * (D_FEAT / 8)];

__global__ __launch_bounds__(512)
void convert_fp16_kernel(const float* __restrict__ x, int n_vec)
{
    const int i = blockIdx.x * blockDim.x + threadIdx.x;
    if (i >= n_vec) return;

    const float4* xf = reinterpret_cast<const float4*>(x);
    const float4 f0 = __ldcs(xf + 2 * i);       // evict-first: dead data
    const float4 f1 = __ldcs(xf + 2 * i + 1);

    const __half2 h0 = __floats2half2_rn(f0.x, f0.y);
    const __half2 h1 = __floats2half2_rn(f0.z, f0.w);
    const __half2 h2 = __floats2half2_rn(f1.x, f1.y);
    const __half2 h3 = __floats2half2_rn(f1.z, f1.w);

    uint4 o;
    o.x = *reinterpret_cast<const unsigned int*>(&h0);
    o.y = *reinterpret_cast<const unsigned int*>(&h1);
    o.z = *reinterpret_cast<const unsigned int*>(&h2);
    o.w = *reinterpret_cast<const unsigned int*>(&h3);
    g_xh[i] = o;
}

__device__ __forceinline__ __half2 u2h(unsigned int u)
{
    return *reinterpret_cast<const __half2*>(&u);
}

__global__ __launch_bounds__(256)
void edge_abs_dot_kernel(const int* __restrict__ r_idx,
                         const int* __restrict__ c_idx,
                         const float* __restrict__ w,
                         const float* __restrict__ b,
                         float* __restrict__ out,
                         int n_edges,
                         int n_nodes)
{
    const int lane  = threadIdx.x & 31;
    const int g     = lane >> 4;        // group 0..1 (one edge each)
    const int t     = lane & 15;        // position within group
    const int gwarp = (blockIdx.x * blockDim.x + threadIdx.x) >> 5;
    const int base  = gwarp << 5;       // 32 edges per warp
    if (base >= n_edges) return;

    // Per-lane w slice (dims 8t..8t+7) converted once to half2.
    const float4* w4 = reinterpret_cast<const float4*>(w);
    const float4 wv0 = __ldg(w4 + 2 * t);
    const float4 wv1 = __ldg(w4 + 2 * t + 1);
    const __half2 wh0 = __floats2half2_rn(wv0.x, wv0.y);
    const __half2 wh1 = __floats2half2_rn(wv0.z, wv0.w);
    const __half2 wh2 = __floats2half2_rn(wv1.x, wv1.y);
    const __half2 wh3 = __floats2half2_rn(wv1.z, wv1.w);
    const float   bb  = __ldg(b);

    // Coalesced index preload; pre-scale to uint4-element offsets so the
    // loop does no multiplies (shfl carries the scaled offset).
    const int eload = min(base + lane, n_edges - 1);
    int ridx = __ldg(r_idx + eload);
    int cidx = __ldg(c_idx + eload);
    ridx = min(max(ridx, 0), n_nodes - 1);
    cidx = min(max(cidx, 0), n_nodes - 1);
    const int roff = ridx << 4;         // row start in uint4 units
    const int coff = cidx << 4;

    // Depth-2 software pipeline: iterations j and j+1 in flight.
    uint4 a_cur, c_cur, a_nxt, c_nxt;
    {
        const int s0 = g;                       // j=0: edge base+g
        const int s1 = 2 + g;                   // j=1: edge base+2+g
        const int ro0 = __shfl_sync(0xffffffffu, roff, s0);
        const int co0 = __shfl_sync(0xffffffffu, coff, s0);
        const int ro1 = __shfl_sync(0xffffffffu, roff, s1);
        const int co1 = __shfl_sync(0xffffffffu, coff, s1);
        a_cur = g_xh[ro0 + t];
        c_cur = g_xh[co0 + t];
        a_nxt = g_xh[ro1 + t];
        c_nxt = g_xh[co1 + t];
    }

    float res = 0.0f;

    #pragma unroll 4
    for (int j = 0; j < 16; ++j) {
        const uint4 a = a_cur;
        const uint4 c = c_cur;
        a_cur = a_nxt;
        c_cur = c_nxt;
        if (j < 14) {
            const int src = 2 * (j + 2) + g;
            const int ro = __shfl_sync(0xffffffffu, roff, src);
            const int co = __shfl_sync(0xffffffffu, coff, src);
            a_nxt = g_xh[ro + t];
            c_nxt = g_xh[co + t];
        }

        // |a - c| in half2 (HABS2 on ALU pipe), 4-term HFMA2 accumulation.
        const __half2 d0 = __habs2(__hsub2(u2h(a.x), u2h(c.x)));
        const __half2 d1 = __habs2(__hsub2(u2h(a.y), u2h(c.y)));
        const __half2 d2 = __habs2(__hsub2(u2h(a.z), u2h(c.z)));
        const __half2 d3 = __habs2(__hsub2(u2h(a.w), u2h(c.w)));

        __half2 p = __hmul2(d0, wh0);
        p = __hfma2(d1, wh1, p);
        p = __hfma2(d2, wh2, p);
        p = __hfma2(d3, wh3, p);

        const float2 pf = __half22float2(p);
        float s = pf.x + pf.y;

        // Reduce within each 16-lane group (2 edges simultaneously), fp32.
        s += __shfl_xor_sync(0xffffffffu, s, 8);
        s += __shfl_xor_sync(0xffffffffu, s, 4);
        s += __shfl_xor_sync(0xffffffffu, s, 2);
        s += __shfl_xor_sync(0xffffffffu, s, 1);

        if (t == j) res = s;    // lane 16g+j holds edge base+2j+g
    }

    // Lane L (g=L>>4, t=L&15) stores edge base + 2t + g.
    // All 32 targets lie in one 128B line -> single store wavefront.
    // Evict-first: out is never re-read.
    const int estore = base + 2 * t + g;
    if (estore < n_edges)
        __stcs(out + estore, res + bb);
}

extern "C" void kernel_launch(void* const* d_in, const int* in_sizes, int n_in,
                              void* d_out, int out_size)
{
    const float* x     = (const float*)d_in[0];   // [N_NODES, 128] fp32
    const int*   r_idx = (const int*)d_in[1];     // [E] int32
    const int*   c_idx = (const int*)d_in[2];     // [E] int32
    const float* w     = (const float*)d_in[3];   // [128, 1] fp32
    const float* b     = (const float*)d_in[4];   // [1] fp32
    float*       out   = (float*)d_out;           // [E] fp32

    const int n_edges = in_sizes[1];              // 600000
    int n_nodes = in_sizes[0] / D_FEAT;           // 100000
    if (n_nodes > MAX_NODES) n_nodes = MAX_NODES;

    // 1) fp32 -> fp16 node table (each thread emits one uint4 = 8 halves)
    const int n_vec = n_nodes * (D_FEAT / 8);     // 1.6M
    convert_fp16_kernel<<<(n_vec + 511) / 512, 512>>>(x, n_vec);

    // 2) edge gather + abs-diff dot
    const int threads = 256;                      // 8 warps/block
    const int edges_per_block = (threads / 32) * 32;   // 256 edges
    const int blocks = (n_edges + edges_per_block - 1) / edges_per_block;
    edge_abs_dot_kernel<<<blocks, threads>>>(r_idx, c_idx, w, b, out,
                                             n_edges, n_nodes);
}